// round 1
// baseline (speedup 1.0000x reference)
#include <cuda_runtime.h>
#include <math.h>
#include <float.h>

#define KB 10
#define TT 70
#define SS 128
#define EE 1024
#define HH 1024
#define VV 32000
#define PAD_ 0
#define START_ 1
#define EOS_ 2
#define NEGF (-1000000000.0f)

// ---------------- device scratch (no cudaMalloc allowed) ----------------
__device__ float d_keys[SS * HH];     // keys[s][h]
__device__ float d_Pt[HH * SS];       // P transposed: Pt[j][s]
__device__ float d_h[KB * HH], d_c[KB * HH], d_prev[KB * HH];
__device__ float d_hn[KB * HH], d_cn[KB * HH], d_on[KB * HH];
__device__ float d_e[KB * SS], d_alpha[KB * SS];
__device__ float d_logits[KB * VV];   // 1.28 MB
__device__ float d_mx[KB], d_lse[KB];
__device__ float d_scores[KB];
__device__ int d_fin[KB];
__device__ int d_tok[2][KB * (TT + 1)];

// ---------------- init ----------------
__global__ void k_init(const float* __restrict__ h0, const float* __restrict__ c0) {
    int tid = blockIdx.x * blockDim.x + threadIdx.x;
    int nt = gridDim.x * blockDim.x;
    for (int i = tid; i < KB * HH; i += nt) {
        d_h[i] = h0[i % HH];
        d_c[i] = c0[i % HH];
        d_prev[i] = 0.f;
    }
    for (int i = tid; i < KB * (TT + 1); i += nt)
        d_tok[0][i] = (i % (TT + 1) == 0) ? START_ : PAD_;
    if (tid < KB) { d_scores[tid] = (tid == 0) ? 0.f : NEGF; d_fin[tid] = 0; }
}

// ---------------- precompute keys / P (tiled 16x16 GEMM, once per launch) ----
// mode 0: out = keys[s][j] = sum_v enc[s][v] * W[j][v]      (W=W_attproj, ld=2048)
// mode 1: out = Pt[j][s]   = sum_v enc[s][v] * W[j][v]      (W=W_comb,    ld=3072, first 2048 cols)
__global__ void k_prep(const float* __restrict__ enc, const float* __restrict__ W,
                       int ldw, int mode) {
    __shared__ float smW[16][129];
    __shared__ float smE[16][129];
    int j0 = blockIdx.x * 16, s0 = blockIdx.y * 16;
    int tid = threadIdx.x;
    int jj = tid & 15, ssn = tid >> 4;
    float acc = 0.f;
    for (int vc = 0; vc < 2 * EE; vc += 128) {
        for (int l = tid; l < 16 * 128; l += 256) {
            int r = l >> 7, cc = l & 127;
            smW[r][cc] = W[(size_t)(j0 + r) * ldw + vc + cc];
            smE[r][cc] = enc[(size_t)(s0 + r) * (2 * EE) + vc + cc];
        }
        __syncthreads();
        #pragma unroll
        for (int x = 0; x < 128; x++) acc += smW[jj][x] * smE[ssn][x];
        __syncthreads();
    }
    int j = j0 + jj, s = s0 + ssn;
    if (mode == 0) d_keys[s * HH + j] = acc;
    else           d_Pt[j * SS + s] = acc;
}

// ---------------- fused gates + LSTM cell (one block per hidden index j) ----
__global__ void k_gates(const float* __restrict__ emb, const float* __restrict__ W_ih,
                        const float* __restrict__ b_ih, const float* __restrict__ W_hh,
                        const float* __restrict__ b_hh, int t, int cur) {
    int j = blockIdx.x, tid = threadIdx.x;
    __shared__ const float* s_eb[KB];
    __shared__ float s_part[8][40];
    __shared__ float s_g[4][KB];
    if (tid < KB) {
        int last = d_tok[cur][tid * (TT + 1) + t];
        s_eb[tid] = emb + (size_t)last * EE;
    }
    __syncthreads();

    float acc[4][KB];
    #pragma unroll
    for (int g = 0; g < 4; g++)
        #pragma unroll
        for (int k = 0; k < KB; k++) acc[g][k] = 0.f;

    const float* w0 = W_ih + (size_t)(0 * HH + j) * 2048;
    const float* w1 = W_ih + (size_t)(1 * HH + j) * 2048;
    const float* w2 = W_ih + (size_t)(2 * HH + j) * 2048;
    const float* w3 = W_ih + (size_t)(3 * HH + j) * 2048;
    const float* u0 = W_hh + (size_t)(0 * HH + j) * 1024;
    const float* u1 = W_hh + (size_t)(1 * HH + j) * 1024;
    const float* u2 = W_hh + (size_t)(2 * HH + j) * 1024;
    const float* u3 = W_hh + (size_t)(3 * HH + j) * 1024;

    for (int v = tid; v < EE; v += 256) {
        float a0 = w0[v], a1 = w1[v], a2 = w2[v], a3 = w3[v];
        #pragma unroll
        for (int k = 0; k < KB; k++) {
            float x = s_eb[k][v];
            acc[0][k] += a0 * x; acc[1][k] += a1 * x;
            acc[2][k] += a2 * x; acc[3][k] += a3 * x;
        }
    }
    for (int v = tid; v < HH; v += 256) {
        float a0 = w0[EE + v], a1 = w1[EE + v], a2 = w2[EE + v], a3 = w3[EE + v];
        float c0v = u0[v], c1v = u1[v], c2v = u2[v], c3v = u3[v];
        #pragma unroll
        for (int k = 0; k < KB; k++) {
            float xp = d_prev[k * HH + v];
            float xh = d_h[k * HH + v];
            acc[0][k] += a0 * xp + c0v * xh;
            acc[1][k] += a1 * xp + c1v * xh;
            acc[2][k] += a2 * xp + c2v * xh;
            acc[3][k] += a3 * xp + c3v * xh;
        }
    }
    int wid = tid >> 5, lane = tid & 31;
    #pragma unroll
    for (int g = 0; g < 4; g++)
        #pragma unroll
        for (int k = 0; k < KB; k++) {
            float v = acc[g][k];
            for (int o = 16; o; o >>= 1) v += __shfl_down_sync(0xffffffffu, v, o);
            if (lane == 0) s_part[wid][g * KB + k] = v;
        }
    __syncthreads();
    if (tid < 40) {
        float v = 0.f;
        #pragma unroll
        for (int w = 0; w < 8; w++) v += s_part[w][tid];
        s_g[tid / KB][tid % KB] = v;
    }
    __syncthreads();
    if (tid < KB) {
        float i_ = s_g[0][tid] + b_ih[j] + b_hh[j];
        float f_ = s_g[1][tid] + b_ih[HH + j] + b_hh[HH + j];
        float g_ = s_g[2][tid] + b_ih[2 * HH + j] + b_hh[2 * HH + j];
        float o_ = s_g[3][tid] + b_ih[3 * HH + j] + b_hh[3 * HH + j];
        float cprev = d_c[tid * HH + j];
        float sf = 1.f / (1.f + expf(-f_));
        float si = 1.f / (1.f + expf(-i_));
        float so = 1.f / (1.f + expf(-o_));
        float cn = sf * cprev + si * tanhf(g_);
        float hn = so * tanhf(cn);
        d_cn[tid * HH + j] = cn;
        d_hn[tid * HH + j] = hn;
    }
}

// ---------------- attention scores e[k][s] ----------------
__global__ void k_e(const int* __restrict__ src_len) {
    int s = blockIdx.x, k = blockIdx.y, tid = threadIdx.x;
    const float* kr = d_keys + s * HH;
    const float* hr = d_hn + k * HH;
    float a = 0.f;
    for (int h = tid; h < HH; h += 128) a += kr[h] * hr[h];
    __shared__ float sm[4];
    for (int o = 16; o; o >>= 1) a += __shfl_down_sync(0xffffffffu, a, o);
    if ((tid & 31) == 0) sm[tid >> 5] = a;
    __syncthreads();
    if (tid == 0) {
        a = sm[0] + sm[1] + sm[2] + sm[3];
        d_e[k * SS + s] = (s >= src_len[0]) ? NEGF : a;
    }
}

// ---------------- softmax over S per beam ----------------
__global__ void k_softmax() {
    int k = blockIdx.x, tid = threadIdx.x;   // 128 threads == SS
    float v = d_e[k * SS + tid];
    __shared__ float smx[4], ssm[4];
    int lane = tid & 31, wid = tid >> 5;
    float m = v;
    for (int o = 16; o; o >>= 1) m = fmaxf(m, __shfl_xor_sync(0xffffffffu, m, o));
    if (lane == 0) smx[wid] = m;
    __syncthreads();
    m = fmaxf(fmaxf(smx[0], smx[1]), fmaxf(smx[2], smx[3]));
    float ex = expf(v - m);
    float s = ex;
    for (int o = 16; o; o >>= 1) s += __shfl_xor_sync(0xffffffffu, s, o);
    if (lane == 0) ssm[wid] = s;
    __syncthreads();
    float tot = ssm[0] + ssm[1] + ssm[2] + ssm[3];
    d_alpha[k * SS + tid] = ex / tot;
}

// ---------------- out[k][j] = tanh(alpha·Pt[j] + Wcomb2[j]·h_new) ----------
__global__ void k_out(const float* __restrict__ W_comb) {
    int j = blockIdx.x, tid = threadIdx.x;   // 128 threads
    float acc[KB];
    #pragma unroll
    for (int k = 0; k < KB; k++) acc[k] = 0.f;
    {
        float p = d_Pt[j * SS + tid];
        #pragma unroll
        for (int k = 0; k < KB; k++) acc[k] += d_alpha[k * SS + tid] * p;
    }
    const float* w = W_comb + (size_t)j * 3072 + 2048;
    for (int h = tid; h < HH; h += 128) {
        float a = w[h];
        #pragma unroll
        for (int k = 0; k < KB; k++) acc[k] += a * d_hn[k * HH + h];
    }
    __shared__ float sp[4][KB];
    int wid = tid >> 5, lane = tid & 31;
    #pragma unroll
    for (int k = 0; k < KB; k++) {
        float v = acc[k];
        for (int o = 16; o; o >>= 1) v += __shfl_down_sync(0xffffffffu, v, o);
        if (lane == 0) sp[wid][k] = v;
    }
    __syncthreads();
    if (tid < KB) {
        float v = sp[0][tid] + sp[1][tid] + sp[2][tid] + sp[3][tid];
        d_on[tid * HH + j] = tanhf(v);
    }
}

// ---------------- vocab logits (warp per vocab row, float4) ----------------
__global__ void k_logits(const float* __restrict__ Wv) {
    int tid = threadIdx.x;
    int lane = tid & 31, w = tid >> 5;
    int v = blockIdx.x * 8 + w;
    const float4* wr = (const float4*)(Wv + (size_t)v * HH);
    float acc[KB];
    #pragma unroll
    for (int k = 0; k < KB; k++) acc[k] = 0.f;
    #pragma unroll
    for (int it = 0; it < 8; it++) {
        float4 a = wr[lane + it * 32];
        #pragma unroll
        for (int k = 0; k < KB; k++) {
            const float4* o = (const float4*)(d_on + k * HH);
            float4 x = o[lane + it * 32];
            acc[k] += a.x * x.x + a.y * x.y + a.z * x.z + a.w * x.w;
        }
    }
    #pragma unroll
    for (int k = 0; k < KB; k++) {
        float s = acc[k];
        for (int o = 16; o; o >>= 1) s += __shfl_down_sync(0xffffffffu, s, o);
        if (lane == 0) d_logits[k * VV + v] = s;
    }
}

// ---------------- per-beam max + logsumexp ----------------
__global__ void k_rowstats() {
    int k = blockIdx.x, tid = threadIdx.x;  // 1024 threads
    int lane = tid & 31, wid = tid >> 5;
    const float* row = d_logits + (size_t)k * VV;
    __shared__ float sm[32];
    __shared__ float bm;
    float m = -FLT_MAX;
    for (int i = tid; i < VV; i += 1024) m = fmaxf(m, row[i]);
    for (int o = 16; o; o >>= 1) m = fmaxf(m, __shfl_xor_sync(0xffffffffu, m, o));
    if (lane == 0) sm[wid] = m;
    __syncthreads();
    if (tid < 32) {
        float v = sm[tid];
        for (int o = 16; o; o >>= 1) v = fmaxf(v, __shfl_xor_sync(0xffffffffu, v, o));
        if (tid == 0) bm = v;
    }
    __syncthreads();
    float mm = bm;
    float s = 0.f;
    for (int i = tid; i < VV; i += 1024) s += expf(row[i] - mm);
    for (int o = 16; o; o >>= 1) s += __shfl_xor_sync(0xffffffffu, s, o);
    if (lane == 0) sm[wid] = s;
    __syncthreads();
    if (tid < 32) {
        float v = sm[tid];
        for (int o = 16; o; o >>= 1) v += __shfl_xor_sync(0xffffffffu, v, o);
        if (tid == 0) { d_mx[k] = mm; d_lse[k] = logf(v); }
    }
}

// ---------------- top-k (exact jax tie-break) + state gather --------------
__global__ void k_topk(int t, int cur) {
    int tid = threadIdx.x;   // 1024
    int lane = tid & 31, wid = tid >> 5;
    __shared__ float s_sc[KB], s_mx[KB], s_ls[KB];
    __shared__ int s_fin[KB];
    __shared__ float s_wv[320];
    __shared__ int s_wi[320];
    __shared__ float s_tv[KB];
    __shared__ int s_ti[KB];
    __shared__ int s_row[KB], s_col[KB], s_nf[KB];
    __shared__ float s_ns[KB];
    if (tid < KB) {
        s_sc[tid] = d_scores[tid]; s_fin[tid] = d_fin[tid];
        s_mx[tid] = d_mx[tid]; s_ls[tid] = d_lse[tid];
    }
    __syncthreads();

    float lv[10]; int li[10];
    #pragma unroll
    for (int p = 0; p < 10; p++) { lv[p] = -FLT_MAX; li[p] = 0x7fffffff; }

    for (int idx = tid; idx < KB * VV; idx += 1024) {
        int k = idx / VV;
        int vtok = idx - k * VV;
        float val;
        if (s_fin[k]) val = (vtok == PAD_) ? s_sc[k] : s_sc[k] + NEGF;
        else          val = s_sc[k] + d_logits[idx] - s_mx[k] - s_ls[k];
        if (val > lv[9]) {
            int cnt = 0;
            #pragma unroll
            for (int p = 0; p < 10; p++) cnt += (lv[p] >= val);
            #pragma unroll
            for (int p = 9; p >= 1; p--) {
                if (p > cnt) { lv[p] = lv[p - 1]; li[p] = li[p - 1]; }
            }
            #pragma unroll
            for (int p = 0; p < 10; p++) {
                if (p == cnt) { lv[p] = val; li[p] = idx; }
            }
        }
    }

    // warp-level merge of 32 sorted lists -> warp top-10
    int head = 0;
    for (int r = 0; r < 10; r++) {
        float cv = -FLT_MAX; int ci = 0x7fffffff;
        #pragma unroll
        for (int p = 0; p < 10; p++) if (p == head) { cv = lv[p]; ci = li[p]; }
        float bv = cv; int bi = ci; int bl = lane;
        for (int o = 16; o; o >>= 1) {
            float ov = __shfl_down_sync(0xffffffffu, bv, o);
            int oi = __shfl_down_sync(0xffffffffu, bi, o);
            int ol = __shfl_down_sync(0xffffffffu, bl, o);
            if (ov > bv || (ov == bv && oi < bi)) { bv = ov; bi = oi; bl = ol; }
        }
        bv = __shfl_sync(0xffffffffu, bv, 0);
        bi = __shfl_sync(0xffffffffu, bi, 0);
        bl = __shfl_sync(0xffffffffu, bl, 0);
        if (lane == bl) head++;
        if (lane == 0) { s_wv[wid * 10 + r] = bv; s_wi[wid * 10 + r] = bi; }
    }
    __syncthreads();

    // final merge of 32 warp lists by warp 0
    if (wid == 0) {
        int hd = 0;
        for (int r = 0; r < 10; r++) {
            float cv = (hd < 10) ? s_wv[lane * 10 + hd] : -FLT_MAX;
            int ci = (hd < 10) ? s_wi[lane * 10 + hd] : 0x7fffffff;
            float bv = cv; int bi = ci; int bl = lane;
            for (int o = 16; o; o >>= 1) {
                float ov = __shfl_down_sync(0xffffffffu, bv, o);
                int oi = __shfl_down_sync(0xffffffffu, bi, o);
                int ol = __shfl_down_sync(0xffffffffu, bl, o);
                if (ov > bv || (ov == bv && oi < bi)) { bv = ov; bi = oi; bl = ol; }
            }
            bv = __shfl_sync(0xffffffffu, bv, 0);
            bi = __shfl_sync(0xffffffffu, bi, 0);
            bl = __shfl_sync(0xffffffffu, bl, 0);
            if (lane == bl) hd++;
            if (lane == 0) { s_tv[r] = bv; s_ti[r] = bi; }
        }
    }
    __syncthreads();

    if (tid < KB) {
        int ix = s_ti[tid];
        int r = ix / VV;
        int col = ix - r * VV;
        s_row[tid] = r; s_col[tid] = col;
        s_ns[tid] = s_tv[tid];
        s_nf[tid] = (s_fin[r] || (col == EOS_)) ? 1 : 0;
    }
    __syncthreads();
    if (tid < KB) { d_scores[tid] = s_ns[tid]; d_fin[tid] = s_nf[tid]; }

    int nxt = cur ^ 1;
    for (int i = tid; i < KB * (TT + 1); i += 1024) {
        int b = i / (TT + 1), p = i - b * (TT + 1);
        int val = (p == t + 1) ? s_col[b] : d_tok[cur][s_row[b] * (TT + 1) + p];
        d_tok[nxt][i] = val;
    }
    for (int i = tid; i < KB * HH; i += 1024) {
        int b = i / HH, h = i - b * HH;
        int r = s_row[b];
        d_h[i] = d_hn[r * HH + h];
        d_c[i] = d_cn[r * HH + h];
        d_prev[i] = d_on[r * HH + h];
    }
}

// ---------------- write output: tokens (as float) then scores -------------
__global__ void k_final(float* __restrict__ out, int n) {
    int tid = blockIdx.x * blockDim.x + threadIdx.x;
    int ntok = KB * (TT + 1);
    int fin = (TT & 1) ^ 0;   // after T steps, current buffer = TT % 2
    for (int i = tid; i < n; i += gridDim.x * blockDim.x) {
        if (i < ntok) out[i] = (float)d_tok[fin & 1][i];
        else if (i < ntok + KB) out[i] = d_scores[i - ntok];
        else out[i] = 0.f;
    }
}

extern "C" void kernel_launch(void* const* d_in, const int* in_sizes, int n_in,
                              void* d_out, int out_size) {
    const float* enc  = (const float*)d_in[0];
    const float* h0   = (const float*)d_in[1];
    const float* c0   = (const float*)d_in[2];
    const float* emb  = (const float*)d_in[3];
    const float* W_ih = (const float*)d_in[4];
    const float* b_ih = (const float*)d_in[5];
    const float* W_hh = (const float*)d_in[6];
    const float* b_hh = (const float*)d_in[7];
    const float* W_at = (const float*)d_in[8];
    const float* W_cb = (const float*)d_in[9];
    const float* W_vb = (const float*)d_in[10];
    const int* srcl   = (const int*)d_in[11];

    k_init<<<40, 256>>>(h0, c0);
    k_prep<<<dim3(HH / 16, SS / 16), 256>>>(enc, W_at, 2 * EE, 0);
    k_prep<<<dim3(HH / 16, SS / 16), 256>>>(enc, W_cb, 2 * EE + HH, 1);

    for (int t = 0; t < TT; t++) {
        int cur = t & 1;
        k_gates<<<HH, 256>>>(emb, W_ih, b_ih, W_hh, b_hh, t, cur);
        k_e<<<dim3(SS, KB), 128>>>(srcl);
        k_softmax<<<KB, 128>>>();
        k_out<<<HH, 128>>>(W_cb);
        k_logits<<<VV / 8, 256>>>(W_vb);
        k_rowstats<<<KB, 1024>>>();
        k_topk<<<1, 1024>>>(t, cur);
    }
    k_final<<<1, 256>>>((float*)d_out, out_size);
}

// round 2
// speedup vs baseline: 1.4090x; 1.4090x over previous
#include <cuda_runtime.h>
#include <math.h>
#include <float.h>

#define KB 10
#define TT 70
#define SS 128
#define EE 1024
#define HH 1024
#define VV 32000
#define PAD_ 0
#define START_ 1
#define EOS_ 2
#define NEGF (-1000000000.0f)
#define NLOG_BLK 250   // logits blocks, 128 vocab rows each

// ---------------- device scratch ----------------
__device__ float d_keys[SS * HH];     // keys[s][h]
__device__ float d_Pt[HH * SS];       // Pt[j][s]
__device__ float d_h[KB * HH], d_c[KB * HH];
__device__ float d_xy[KB * 2048];     // [emb(1024) | prevOut(1024)] per beam
__device__ float d_hn[KB * HH], d_cn[KB * HH], d_on[KB * HH];
__device__ float d_alpha[KB * SS];
__device__ float d_gates[KB * 4 * HH];   // [k][row]
__device__ float d_scores[KB];
__device__ int d_fin[KB];
__device__ int d_row[KB], d_col[KB];
__device__ int d_tok[2][KB * (TT + 1)];
// logits partials
__device__ float d_pmax[NLOG_BLK * KB], d_psum[NLOG_BLK * KB];
__device__ float d_ptv[NLOG_BLK * KB * 10];
__device__ int   d_pti[NLOG_BLK * KB * 10];

__device__ __forceinline__ float sigm(float x) { return 1.f / (1.f + expf(-x)); }

// ---------------- init ----------------
__global__ void k_init(const float* __restrict__ h0, const float* __restrict__ c0,
                       const float* __restrict__ emb) {
    int tid = blockIdx.x * blockDim.x + threadIdx.x;
    int nt = gridDim.x * blockDim.x;
    for (int i = tid; i < KB * HH; i += nt) {
        int h = i & 1023;
        d_h[i] = h0[h];
        d_c[i] = c0[h];
    }
    for (int i = tid; i < KB * 2048; i += nt) {
        int b = i >> 11, p = i & 2047;
        d_xy[i] = (p < 1024) ? emb[(size_t)START_ * EE + p] : 0.f;
        (void)b;
    }
    for (int i = tid; i < KB * (TT + 1); i += nt)
        d_tok[0][i] = (i % (TT + 1) == 0) ? START_ : PAD_;
    if (tid < KB) { d_scores[tid] = (tid == 0) ? 0.f : NEGF; d_fin[tid] = 0; }
}

// ---------------- precompute keys / Pt ----------------
__global__ void k_prep(const float* __restrict__ enc, const float* __restrict__ W,
                       int ldw, int mode) {
    __shared__ float smW[16][129];
    __shared__ float smE[16][129];
    int j0 = blockIdx.x * 16, s0 = blockIdx.y * 16;
    int tid = threadIdx.x;
    int jj = tid & 15, ssn = tid >> 4;
    float acc = 0.f;
    for (int vc = 0; vc < 2 * EE; vc += 128) {
        for (int l = tid; l < 16 * 128; l += 256) {
            int r = l >> 7, cc = l & 127;
            smW[r][cc] = W[(size_t)(j0 + r) * ldw + vc + cc];
            smE[r][cc] = enc[(size_t)(s0 + r) * (2 * EE) + vc + cc];
        }
        __syncthreads();
        #pragma unroll
        for (int x = 0; x < 128; x++) acc += smW[jj][x] * smE[ssn][x];
        __syncthreads();
    }
    int j = j0 + jj, s = s0 + ssn;
    if (mode == 0) d_keys[s * HH + j] = acc;
    else           d_Pt[j * SS + s] = acc;
}

// ---------------- gates GEMV: d_gates[k][row] = W[row]·y_k + b ----------------
__global__ void __launch_bounds__(256) k_gates(
        const float* __restrict__ W_ih, const float* __restrict__ b_ih,
        const float* __restrict__ W_hh, const float* __restrict__ b_hh) {
    int wid = threadIdx.x >> 5, lane = threadIdx.x & 31;
    int pair = blockIdx.x * 8 + wid;   // 0..2047
    int r0 = pair * 2, r1 = r0 + 1;
    float acc[2][KB];
    #pragma unroll
    for (int r = 0; r < 2; r++)
        #pragma unroll
        for (int k = 0; k < KB; k++) acc[r][k] = 0.f;

    const float4* wa = (const float4*)(W_ih + (size_t)r0 * 2048);
    const float4* wb = (const float4*)(W_ih + (size_t)r1 * 2048);
    #pragma unroll 4
    for (int it = 0; it < 16; it++) {
        int ix = it * 32 + lane;
        float4 a0 = wa[ix], a1 = wb[ix];
        #pragma unroll
        for (int k = 0; k < KB; k++) {
            float4 y = ((const float4*)(d_xy + k * 2048))[ix];
            acc[0][k] += a0.x * y.x + a0.y * y.y + a0.z * y.z + a0.w * y.w;
            acc[1][k] += a1.x * y.x + a1.y * y.y + a1.z * y.z + a1.w * y.w;
        }
    }
    const float4* ua = (const float4*)(W_hh + (size_t)r0 * 1024);
    const float4* ub = (const float4*)(W_hh + (size_t)r1 * 1024);
    #pragma unroll 4
    for (int it = 0; it < 8; it++) {
        int ix = it * 32 + lane;
        float4 a0 = ua[ix], a1 = ub[ix];
        #pragma unroll
        for (int k = 0; k < KB; k++) {
            float4 y = ((const float4*)(d_h + k * 1024))[ix];
            acc[0][k] += a0.x * y.x + a0.y * y.y + a0.z * y.z + a0.w * y.w;
            acc[1][k] += a1.x * y.x + a1.y * y.y + a1.z * y.z + a1.w * y.w;
        }
    }
    float bs0 = b_ih[r0] + b_hh[r0];
    float bs1 = b_ih[r1] + b_hh[r1];
    #pragma unroll
    for (int k = 0; k < KB; k++) {
        float v0 = acc[0][k], v1 = acc[1][k];
        for (int o = 16; o; o >>= 1) {
            v0 += __shfl_down_sync(0xffffffffu, v0, o);
            v1 += __shfl_down_sync(0xffffffffu, v1, o);
        }
        if (lane == 0) {
            d_gates[k * 4096 + r0] = v0 + bs0;
            d_gates[k * 4096 + r1] = v1 + bs1;
        }
    }
}

// ------------- LSTM cell + attention scores + softmax (block per beam) -------
__global__ void __launch_bounds__(1024) k_attn(const int* __restrict__ src_len) {
    int k = blockIdx.x;
    int tid = threadIdx.x;
    __shared__ float s_h[1024];
    __shared__ float s_e[128];
    __shared__ float s_m, s_t;

    int j = tid;
    float gi = d_gates[k * 4096 + j];
    float gf = d_gates[k * 4096 + 1024 + j];
    float gg = d_gates[k * 4096 + 2048 + j];
    float go = d_gates[k * 4096 + 3072 + j];
    float cp = d_c[k * 1024 + j];
    float cn = sigm(gf) * cp + sigm(gi) * tanhf(gg);
    float hn = sigm(go) * tanhf(cn);
    d_cn[k * 1024 + j] = cn;
    d_hn[k * 1024 + j] = hn;
    s_h[j] = hn;
    __syncthreads();

    int wid = tid >> 5, lane = tid & 31;
    int slen = src_len[0];
    #pragma unroll
    for (int si = 0; si < 4; si++) {
        int s = wid * 4 + si;
        const float4* kr = (const float4*)(d_keys + s * 1024);
        const float4* hh = (const float4*)s_h;
        float a = 0.f;
        #pragma unroll
        for (int it = 0; it < 8; it++) {
            float4 x = kr[it * 32 + lane];
            float4 y = hh[it * 32 + lane];
            a += x.x * y.x + x.y * y.y + x.z * y.z + x.w * y.w;
        }
        for (int o = 16; o; o >>= 1) a += __shfl_down_sync(0xffffffffu, a, o);
        if (lane == 0) s_e[s] = (s >= slen) ? NEGF : a;
    }
    __syncthreads();
    if (wid == 0) {
        float v0 = s_e[lane], v1 = s_e[lane + 32], v2 = s_e[lane + 64], v3 = s_e[lane + 96];
        float m = fmaxf(fmaxf(v0, v1), fmaxf(v2, v3));
        for (int o = 16; o; o >>= 1) m = fmaxf(m, __shfl_xor_sync(0xffffffffu, m, o));
        float t = expf(v0 - m) + expf(v1 - m) + expf(v2 - m) + expf(v3 - m);
        for (int o = 16; o; o >>= 1) t += __shfl_xor_sync(0xffffffffu, t, o);
        if (lane == 0) { s_m = m; s_t = t; }
    }
    __syncthreads();
    if (tid < 128) d_alpha[k * 128 + tid] = expf(s_e[tid] - s_m) / s_t;
}

// ---------------- out[k][j] = tanh(alpha·Pt[j] + Wcomb2[j]·h_new) ------------
__global__ void __launch_bounds__(128) k_out(const float* __restrict__ W_comb) {
    int j = blockIdx.x, tid = threadIdx.x;   // 128 threads
    float acc[KB];
    #pragma unroll
    for (int k = 0; k < KB; k++) acc[k] = 0.f;
    {
        float p = d_Pt[j * 128 + tid];
        #pragma unroll
        for (int k = 0; k < KB; k++) acc[k] += d_alpha[k * 128 + tid] * p;
    }
    const float4* w4 = (const float4*)(W_comb + (size_t)j * 3072 + 2048);
    #pragma unroll
    for (int it = 0; it < 2; it++) {
        int ix = it * 128 + tid;
        float4 a = w4[ix];
        #pragma unroll
        for (int k = 0; k < KB; k++) {
            float4 y = ((const float4*)(d_hn + k * 1024))[ix];
            acc[k] += a.x * y.x + a.y * y.y + a.z * y.z + a.w * y.w;
        }
    }
    __shared__ float sp[4][KB];
    int wid = tid >> 5, lane = tid & 31;
    #pragma unroll
    for (int k = 0; k < KB; k++) {
        float v = acc[k];
        for (int o = 16; o; o >>= 1) v += __shfl_down_sync(0xffffffffu, v, o);
        if (lane == 0) sp[wid][k] = v;
    }
    __syncthreads();
    if (tid < KB) {
        float v = sp[0][tid] + sp[1][tid] + sp[2][tid] + sp[3][tid];
        d_on[tid * HH + j] = tanhf(v);
    }
}

// ----- vocab logits fused with per-block per-beam top-10 + (max,sumexp) -----
__global__ void __launch_bounds__(256) k_logits(const float* __restrict__ Wv) {
    __shared__ float s_on[KB * 1024];   // 40KB
    __shared__ float s_lg[KB][128];     // 5KB
    int tid = threadIdx.x;
    int wid = tid >> 5, lane = tid & 31;
    {
        const float4* src = (const float4*)d_on;
        float4* dst = (float4*)s_on;
        for (int i = tid; i < KB * 256; i += 256) dst[i] = src[i];
    }
    __syncthreads();
    int base = blockIdx.x * 128;

    for (int qq = 0; qq < 4; qq++) {
        int q = wid * 4 + qq;            // 0..31 local quad
        int r = base + q * 4;
        float acc[4][KB];
        #pragma unroll
        for (int rr = 0; rr < 4; rr++)
            #pragma unroll
            for (int k = 0; k < KB; k++) acc[rr][k] = 0.f;
        const float4* w0 = (const float4*)(Wv + (size_t)r * 1024);
        const float4* w1 = w0 + 256;
        const float4* w2 = w0 + 512;
        const float4* w3 = w0 + 768;
        #pragma unroll
        for (int it = 0; it < 8; it++) {
            int ix = it * 32 + lane;
            float4 a0 = w0[ix], a1 = w1[ix], a2 = w2[ix], a3 = w3[ix];
            #pragma unroll
            for (int k = 0; k < KB; k++) {
                float4 o = ((const float4*)(s_on + k * 1024))[ix];
                acc[0][k] += a0.x * o.x + a0.y * o.y + a0.z * o.z + a0.w * o.w;
                acc[1][k] += a1.x * o.x + a1.y * o.y + a1.z * o.z + a1.w * o.w;
                acc[2][k] += a2.x * o.x + a2.y * o.y + a2.z * o.z + a2.w * o.w;
                acc[3][k] += a3.x * o.x + a3.y * o.y + a3.z * o.z + a3.w * o.w;
            }
        }
        #pragma unroll
        for (int rr = 0; rr < 4; rr++)
            #pragma unroll
            for (int k = 0; k < KB; k++) {
                float v = acc[rr][k];
                for (int o = 16; o; o >>= 1) v += __shfl_down_sync(0xffffffffu, v, o);
                if (lane == 0) s_lg[k][q * 4 + rr] = v;
            }
    }
    __syncthreads();

    // per-beam block reduction: max, sumexp, top-10 (warp per beam)
    for (int k = wid; k < KB; k += 8) {
        float4 vv = ((const float4*)s_lg[k])[lane];
        float v0 = vv.x, v1 = vv.y, v2 = vv.z, v3 = vv.w;
        int gbase = k * VV + base + lane * 4;
        int i0 = gbase, i1 = gbase + 1, i2 = gbase + 2, i3 = gbase + 3;
        // sort 4 desc (stable; idx already ascending)
        #define CSWAP(va, ia, vb, ib) { if (vb > va) { float tv = va; va = vb; vb = tv; int ti = ia; ia = ib; ib = ti; } }
        CSWAP(v0, i0, v1, i1); CSWAP(v2, i2, v3, i3);
        CSWAP(v0, i0, v2, i2); CSWAP(v1, i1, v3, i3);
        CSWAP(v1, i1, v2, i2);
        #undef CSWAP
        // max over warp (v0 is local max)
        float m = v0;
        for (int o = 16; o; o >>= 1) m = fmaxf(m, __shfl_xor_sync(0xffffffffu, m, o));
        float ssum = expf(v0 - m) + expf(v1 - m) + expf(v2 - m) + expf(v3 - m);
        for (int o = 16; o; o >>= 1) ssum += __shfl_xor_sync(0xffffffffu, ssum, o);
        if (lane == 0) {
            d_pmax[blockIdx.x * KB + k] = m;
            d_psum[blockIdx.x * KB + k] = ssum;
        }
        // top-10 via head merge of per-lane sorted 4-lists
        int head = 0;
        for (int r2 = 0; r2 < 10; r2++) {
            float cv; int ci;
            if      (head == 0) { cv = v0; ci = i0; }
            else if (head == 1) { cv = v1; ci = i1; }
            else if (head == 2) { cv = v2; ci = i2; }
            else if (head == 3) { cv = v3; ci = i3; }
            else { cv = -FLT_MAX; ci = 0x7fffffff; }
            float bv = cv; int bi = ci; int bl = lane;
            for (int o = 16; o; o >>= 1) {
                float ov = __shfl_down_sync(0xffffffffu, bv, o);
                int oi = __shfl_down_sync(0xffffffffu, bi, o);
                int ol = __shfl_down_sync(0xffffffffu, bl, o);
                if (ov > bv || (ov == bv && oi < bi)) { bv = ov; bi = oi; bl = ol; }
            }
            bv = __shfl_sync(0xffffffffu, bv, 0);
            bi = __shfl_sync(0xffffffffu, bi, 0);
            bl = __shfl_sync(0xffffffffu, bl, 0);
            if (lane == bl) head++;
            if (lane == 0) {
                d_ptv[(blockIdx.x * KB + k) * 10 + r2] = bv;
                d_pti[(blockIdx.x * KB + k) * 10 + r2] = bi;
            }
        }
    }
}

// ------------- merge partials: exact lse, global top-10, token update --------
__global__ void __launch_bounds__(1024) k_merge(int t, int cur) {
    int tid = threadIdx.x;
    int wid = tid >> 5, lane = tid & 31;
    __shared__ float s_mx[KB], s_ls[KB], s_sc[KB];
    __shared__ int s_fin[KB];
    __shared__ float s_wv[320];
    __shared__ int s_wi[320];
    __shared__ float s_tv[KB];
    __shared__ int s_ti[KB];
    __shared__ int s_row[KB], s_col[KB];
    if (tid < KB) { s_sc[tid] = d_scores[tid]; s_fin[tid] = d_fin[tid]; }
    __syncthreads();

    if (wid < KB) {
        int k = wid;
        float m = -FLT_MAX;
        for (int b = lane; b < NLOG_BLK; b += 32) m = fmaxf(m, d_pmax[b * KB + k]);
        for (int o = 16; o; o >>= 1) m = fmaxf(m, __shfl_xor_sync(0xffffffffu, m, o));
        float s = 0.f;
        for (int b = lane; b < NLOG_BLK; b += 32)
            s += d_psum[b * KB + k] * expf(d_pmax[b * KB + k] - m);
        for (int o = 16; o; o >>= 1) s += __shfl_xor_sync(0xffffffffu, s, o);
        if (lane == 0) { s_mx[k] = m; s_ls[k] = logf(s); }
    }
    __syncthreads();

    float lv[10]; int li[10];
    #pragma unroll
    for (int p = 0; p < 10; p++) { lv[p] = -FLT_MAX; li[p] = 0x7fffffff; }

    const int NE = NLOG_BLK * KB * 10;
    for (int e = tid; e < NE; e += 1024) {
        int k = (e / 10) % KB;
        if (s_fin[k]) continue;
        float val = s_sc[k] + d_ptv[e] - s_mx[k] - s_ls[k];
        int idx = d_pti[e];
        if (val > lv[9] || (val == lv[9] && idx < li[9])) {
            int cnt = 0;
            #pragma unroll
            for (int p = 0; p < 10; p++)
                cnt += (lv[p] > val) || (lv[p] == val && li[p] < idx);
            #pragma unroll
            for (int p = 9; p >= 1; p--)
                if (p > cnt) { lv[p] = lv[p - 1]; li[p] = li[p - 1]; }
            #pragma unroll
            for (int p = 0; p < 10; p++)
                if (p == cnt) { lv[p] = val; li[p] = idx; }
        }
    }
    // inject finished beams' PAD candidates into thread tid's list
    if (tid < KB && s_fin[tid]) {
        float val = s_sc[tid];
        int idx = tid * VV + PAD_;
        if (val > lv[9] || (val == lv[9] && idx < li[9])) {
            int cnt = 0;
            #pragma unroll
            for (int p = 0; p < 10; p++)
                cnt += (lv[p] > val) || (lv[p] == val && li[p] < idx);
            #pragma unroll
            for (int p = 9; p >= 1; p--)
                if (p > cnt) { lv[p] = lv[p - 1]; li[p] = li[p - 1]; }
            #pragma unroll
            for (int p = 0; p < 10; p++)
                if (p == cnt) { lv[p] = val; li[p] = idx; }
        }
    }

    // warp merge of 32 sorted lists -> warp top-10
    int head = 0;
    for (int r = 0; r < 10; r++) {
        float cv = -FLT_MAX; int ci = 0x7fffffff;
        #pragma unroll
        for (int p = 0; p < 10; p++) if (p == head) { cv = lv[p]; ci = li[p]; }
        float bv = cv; int bi = ci; int bl = lane;
        for (int o = 16; o; o >>= 1) {
            float ov = __shfl_down_sync(0xffffffffu, bv, o);
            int oi = __shfl_down_sync(0xffffffffu, bi, o);
            int ol = __shfl_down_sync(0xffffffffu, bl, o);
            if (ov > bv || (ov == bv && oi < bi)) { bv = ov; bi = oi; bl = ol; }
        }
        bv = __shfl_sync(0xffffffffu, bv, 0);
        bi = __shfl_sync(0xffffffffu, bi, 0);
        bl = __shfl_sync(0xffffffffu, bl, 0);
        if (lane == bl) head++;
        if (lane == 0) { s_wv[wid * 10 + r] = bv; s_wi[wid * 10 + r] = bi; }
    }
    __syncthreads();
    if (wid == 0) {
        int hd = 0;
        for (int r = 0; r < 10; r++) {
            float cv = (hd < 10) ? s_wv[lane * 10 + hd] : -FLT_MAX;
            int ci = (hd < 10) ? s_wi[lane * 10 + hd] : 0x7fffffff;
            float bv = cv; int bi = ci; int bl = lane;
            for (int o = 16; o; o >>= 1) {
                float ov = __shfl_down_sync(0xffffffffu, bv, o);
                int oi = __shfl_down_sync(0xffffffffu, bi, o);
                int ol = __shfl_down_sync(0xffffffffu, bl, o);
                if (ov > bv || (ov == bv && oi < bi)) { bv = ov; bi = oi; bl = ol; }
            }
            bv = __shfl_sync(0xffffffffu, bv, 0);
            bi = __shfl_sync(0xffffffffu, bi, 0);
            bl = __shfl_sync(0xffffffffu, bl, 0);
            if (lane == bl) hd++;
            if (lane == 0) { s_tv[r] = bv; s_ti[r] = bi; }
        }
    }
    __syncthreads();

    if (tid < KB) {
        int ix = s_ti[tid];
        int r = ix / VV;
        int col = ix - r * VV;
        s_row[tid] = r; s_col[tid] = col;
        d_scores[tid] = s_tv[tid];
        d_fin[tid] = (s_fin[r] || (col == EOS_)) ? 1 : 0;
        d_row[tid] = r; d_col[tid] = col;
    }
    __syncthreads();
    int nxt = cur ^ 1;
    for (int i = tid; i < KB * (TT + 1); i += 1024) {
        int b = i / (TT + 1), p = i - b * (TT + 1);
        int val = (p == t + 1) ? s_col[b] : d_tok[cur][s_row[b] * (TT + 1) + p];
        d_tok[nxt][i] = val;
    }
}

// ---------------- gather: reorder states by beam, build next-step xy ---------
__global__ void k_gather(const float* __restrict__ emb) {
    int i = blockIdx.x * blockDim.x + threadIdx.x;   // 10240 threads
    if (i >= KB * 1024) return;
    int b = i >> 10, h2 = i & 1023;
    int r = d_row[b];
    int col = d_col[b];
    d_h[i] = d_hn[r * 1024 + h2];
    d_c[i] = d_cn[r * 1024 + h2];
    d_xy[b * 2048 + 1024 + h2] = d_on[r * 1024 + h2];
    d_xy[b * 2048 + h2] = emb[(size_t)col * EE + h2];
}

// ---------------- output ----------------
__global__ void k_final(float* __restrict__ out, int n) {
    int tid = blockIdx.x * blockDim.x + threadIdx.x;
    int ntok = KB * (TT + 1);
    int fin = TT & 1;
    for (int i = tid; i < n; i += gridDim.x * blockDim.x) {
        if (i < ntok) out[i] = (float)d_tok[fin][i];
        else if (i < ntok + KB) out[i] = d_scores[i - ntok];
        else out[i] = 0.f;
    }
}

extern "C" void kernel_launch(void* const* d_in, const int* in_sizes, int n_in,
                              void* d_out, int out_size) {
    const float* enc  = (const float*)d_in[0];
    const float* h0   = (const float*)d_in[1];
    const float* c0   = (const float*)d_in[2];
    const float* emb  = (const float*)d_in[3];
    const float* W_ih = (const float*)d_in[4];
    const float* b_ih = (const float*)d_in[5];
    const float* W_hh = (const float*)d_in[6];
    const float* b_hh = (const float*)d_in[7];
    const float* W_at = (const float*)d_in[8];
    const float* W_cb = (const float*)d_in[9];
    const float* W_vb = (const float*)d_in[10];
    const int* srcl   = (const int*)d_in[11];

    k_init<<<48, 256>>>(h0, c0, emb);
    k_prep<<<dim3(HH / 16, SS / 16), 256>>>(enc, W_at, 2 * EE, 0);
    k_prep<<<dim3(HH / 16, SS / 16), 256>>>(enc, W_cb, 2 * EE + HH, 1);

    for (int t = 0; t < TT; t++) {
        int cur = t & 1;
        k_gates<<<256, 256>>>(W_ih, b_ih, W_hh, b_hh);
        k_attn<<<KB, 1024>>>(srcl);
        k_out<<<HH, 128>>>(W_cb);
        k_logits<<<NLOG_BLK, 256>>>(W_vb);
        k_merge<<<1, 1024>>>(t, cur);
        k_gather<<<40, 256>>>(emb);
    }
    k_final<<<1, 256>>>((float*)d_out, out_size);
}